// round 14
// baseline (speedup 1.0000x reference)
#include <cuda_runtime.h>
#include <cuda_fp16.h>
#include <math.h>

#define B_ 4
#define N_ 65536
#define K_ 16
#define D_ 8
#define EPS_ 1e-6f
#define SLOPE_ 0.2f

#define NBLK 592          // 148 SMs x 4 blocks, all co-resident (launch_bounds enforces)
#define TPB 256
#define TT (NBLK * TPB)

// 32B record per point: [x,y,z,pad (fp32) | f0..f7 (fp16)]
__device__ float4 g_rec[(size_t)B_ * N_ * 2];
__device__ double g_sums[16];                  // sum_y[0..7], sum_y2[8..15]
__device__ unsigned g_bar0, g_bar1, g_done;    // zero at load; reset by last block each launch

// 256-bit global load (sm_100+): whole 32B record in ONE instruction
__device__ __forceinline__ void ldg256(const float4* p, float4& a, float4& b) {
    asm volatile(
        "ld.global.v8.b32 {%0,%1,%2,%3,%4,%5,%6,%7}, [%8];"
        : "=f"(a.x), "=f"(a.y), "=f"(a.z), "=f"(a.w),
          "=f"(b.x), "=f"(b.y), "=f"(b.z), "=f"(b.w)
        : "l"(p));
}

// software grid barrier: all NBLK blocks are co-resident, so spin is deadlock-free
__device__ __forceinline__ void grid_sync(unsigned* cnt) {
    __syncthreads();
    if (threadIdx.x == 0) {
        __threadfence();
        atomicAdd(cnt, 1u);
        volatile unsigned* v = cnt;
        while (*v < NBLK) { }
        __threadfence();
    }
    __syncthreads();
}

__global__ void __launch_bounds__(TPB, 4) k_all(const float* __restrict__ coords,
                                                const float* __restrict__ feats,
                                                const int*   __restrict__ idx,
                                                const float* __restrict__ conv_w,
                                                const float* __restrict__ conv_b,
                                                const float* __restrict__ gamma,
                                                const float* __restrict__ beta,
                                                float* __restrict__ out) {
    __shared__ float s_wp[64];   // [0..7]=W0, [8..31]=A, [32..55]=C, [56..63]=bias
    __shared__ float s_bn[16];   // scale[0..7], shift[8..15]
    __shared__ float ps[16];

    int tid = threadIdx.x;
    if (tid < 8) {
        int o = tid;
        const float* w = conv_w + o * 10;
        s_wp[o] = w[0];
        s_wp[8 + o*3 + 0] = w[1] + w[4];
        s_wp[8 + o*3 + 1] = w[2] + w[5];
        s_wp[8 + o*3 + 2] = w[3] + w[6];
        s_wp[32 + o*3 + 0] = w[7] - w[1];
        s_wp[32 + o*3 + 1] = w[8] - w[2];
        s_wp[32 + o*3 + 2] = w[9] - w[3];
        s_wp[56 + o] = conv_b[o];
    }
    if (blockIdx.x == 0 && tid < 16) g_sums[tid] = 0.0;
    __syncthreads();

    int gtid = blockIdx.x * TPB + tid;

    // ---------------- Phase A: pack records ----------------
    for (int t = gtid; t < B_ * N_; t += TT) {
        int b = t >> 16;
        int n = t & (N_ - 1);
        float cx = coords[(size_t)t * 3 + 0];
        float cy = coords[(size_t)t * 3 + 1];
        float cz = coords[(size_t)t * 3 + 2];
        const float* fb = feats + (size_t)b * D_ * N_ + n;
        __half2 h01 = __floats2half2_rn(fb[0 * N_], fb[1 * N_]);
        __half2 h23 = __floats2half2_rn(fb[2 * N_], fb[3 * N_]);
        __half2 h45 = __floats2half2_rn(fb[4 * N_], fb[5 * N_]);
        __half2 h67 = __floats2half2_rn(fb[6 * N_], fb[7 * N_]);
        float4 hv;
        hv.x = __uint_as_float(*(const unsigned*)&h01);
        hv.y = __uint_as_float(*(const unsigned*)&h23);
        hv.z = __uint_as_float(*(const unsigned*)&h45);
        hv.w = __uint_as_float(*(const unsigned*)&h67);
        g_rec[(size_t)t * 2]     = make_float4(cx, cy, cz, 0.f);
        g_rec[(size_t)t * 2 + 1] = hv;
    }

    grid_sync(&g_bar0);

    // ---------------- Phase B: BN statistics ----------------
    {
        float sy[8], sy2[8];
        #pragma unroll
        for (int o = 0; o < 8; o++) { sy[o] = 0.f; sy2[o] = 0.f; }

        for (int t = gtid; t < B_ * N_; t += TT) {
            int base = (t >> 16) << 16;
            float4 ext = g_rec[(size_t)t * 2];
            float e[8];
            #pragma unroll
            for (int o = 0; o < 8; o++)
                e[o] = s_wp[56 + o] + s_wp[8 + o*3] * ext.x + s_wp[9 + o*3] * ext.y
                     + s_wp[10 + o*3] * ext.z;

            const int4* ip = (const int4*)idx + (size_t)t * 4;
            #pragma unroll
            for (int kk = 0; kk < 4; kk++) {
                int4 j4 = ip[kk];
                int js[4] = {j4.x, j4.y, j4.z, j4.w};
                #pragma unroll
                for (int u = 0; u < 4; u++) {
                    float4 nb = g_rec[(size_t)(base + js[u]) * 2];
                    float rx = ext.x - nb.x, ry = ext.y - nb.y, rz = ext.z - nb.z;
                    float d = sqrtf(rx * rx + ry * ry + rz * rz);
                    #pragma unroll
                    for (int o = 0; o < 8; o++) {
                        float y = e[o] + s_wp[o] * d + s_wp[32 + o*3] * nb.x
                                + s_wp[33 + o*3] * nb.y + s_wp[34 + o*3] * nb.z;
                        sy[o]  += y;
                        sy2[o] += y * y;
                    }
                }
            }
        }

        #pragma unroll
        for (int o = 0; o < 8; o++) {
            #pragma unroll
            for (int off = 16; off > 0; off >>= 1) {
                sy[o]  += __shfl_down_sync(0xffffffffu, sy[o],  off);
                sy2[o] += __shfl_down_sync(0xffffffffu, sy2[o], off);
            }
        }
        if (tid < 16) ps[tid] = 0.f;
        __syncthreads();
        if ((tid & 31) == 0) {
            #pragma unroll
            for (int o = 0; o < 8; o++) {
                atomicAdd(&ps[o],     sy[o]);
                atomicAdd(&ps[8 + o], sy2[o]);
            }
        }
        __syncthreads();
        if (tid < 16) atomicAdd(&g_sums[tid], (double)ps[tid]);
    }

    grid_sync(&g_bar1);

    // ---------------- Phase C: normalize + write outputs ----------------
    if (tid < 8) {
        int o = tid;
        double M    = (double)B_ * N_ * K_;
        double mean = __ldcg(&g_sums[o]) / M;
        double var  = __ldcg(&g_sums[8 + o]) / M - mean * mean;
        float  sc   = (float)((double)gamma[o] / sqrt(var + (double)EPS_));
        s_bn[o]     = sc;
        s_bn[8 + o] = beta[o] - (float)mean * sc;
    }
    __syncthreads();

    const size_t plane = (size_t)N_ * K_;           // 1,048,576
    for (int t = gtid; t < B_ * N_ * K_ / 2; t += TT) {
        int pn = t >> 3;               // b*N + n
        int b  = pn >> 16;

        int2 j2 = ((const int2*)idx)[t];
        float4 nb0, hf0, nb1, hf1;
        ldg256(g_rec + ((size_t)((b << 16) | j2.x) << 1), nb0, hf0);
        ldg256(g_rec + ((size_t)((b << 16) | j2.y) << 1), nb1, hf1);

        float4 ext = g_rec[(size_t)pn << 1];
        float rx0 = ext.x - nb0.x, ry0 = ext.y - nb0.y, rz0 = ext.z - nb0.z;
        float rx1 = ext.x - nb1.x, ry1 = ext.y - nb1.y, rz1 = ext.z - nb1.z;
        float d0 = sqrtf(rx0 * rx0 + ry0 * ry0 + rz0 * rz0);
        float d1 = sqrtf(rx1 * rx1 + ry1 * ry1 + rz1 * rz1);

        size_t inner = ((size_t)(t & (int)(plane / 2 - 1))) * 2;
        float* o1 = out + (size_t)b * 16 * plane + inner;
        float* o2 = out + (size_t)B_ * 16 * plane + (size_t)b * 8 * plane + inner;

        // neighbour-feature channels 0..7
        {
            const unsigned* u0 = (const unsigned*)&hf0;
            const unsigned* u1 = (const unsigned*)&hf1;
            #pragma unroll
            for (int q = 0; q < 4; q++) {
                float2 a  = __half22float2(*(const __half2*)&u0[q]);
                float2 b2 = __half22float2(*(const __half2*)&u1[q]);
                __stcs((float2*)(o1 + (size_t)(2 * q + 0) * plane), make_float2(a.x, b2.x));
                __stcs((float2*)(o1 + (size_t)(2 * q + 1) * plane), make_float2(a.y, b2.y));
            }
        }

        // BN + LeakyReLU channels
        #pragma unroll
        for (int o = 0; o < 8; o++) {
            float eo = s_wp[56 + o] + s_wp[8 + o*3] * ext.x + s_wp[9 + o*3] * ext.y
                     + s_wp[10 + o*3] * ext.z;
            float y0 = eo + s_wp[o] * d0 + s_wp[32 + o*3] * nb0.x
                     + s_wp[33 + o*3] * nb0.y + s_wp[34 + o*3] * nb0.z;
            float y1 = eo + s_wp[o] * d1 + s_wp[32 + o*3] * nb1.x
                     + s_wp[33 + o*3] * nb1.y + s_wp[34 + o*3] * nb1.z;
            float z0 = fmaf(y0, s_bn[o], s_bn[8 + o]);
            float z1 = fmaf(y1, s_bn[o], s_bn[8 + o]);
            z0 = fmaxf(z0, SLOPE_ * z0);
            z1 = fmaxf(z1, SLOPE_ * z1);
            float2 zz = make_float2(z0, z1);
            __stcs((float2*)(o1 + (size_t)(8 + o) * plane), zz);
            __stcs((float2*)(o2 + (size_t)o * plane), zz);
        }
    }

    // reset barrier state for next graph replay (last block to finish does it)
    __syncthreads();
    if (tid == 0) {
        __threadfence();
        unsigned d = atomicAdd(&g_done, 1u);
        if (d == NBLK - 1) {
            atomicExch(&g_bar0, 0u);
            atomicExch(&g_bar1, 0u);
            atomicExch(&g_done, 0u);
        }
    }
}

extern "C" void kernel_launch(void* const* d_in, const int* in_sizes, int n_in,
                              void* d_out, int out_size) {
    const float* coords = (const float*)d_in[0];
    const float* feats  = (const float*)d_in[1];
    const int*   idx    = (const int*)d_in[2];
    const float* conv_w = (const float*)d_in[3];
    const float* conv_b = (const float*)d_in[4];
    const float* gamma  = (const float*)d_in[5];
    const float* beta   = (const float*)d_in[6];
    float* out = (float*)d_out;

    k_all<<<NBLK, TPB>>>(coords, feats, idx, conv_w, conv_b, gamma, beta, out);
}

// round 15
// speedup vs baseline: 1.2724x; 1.2724x over previous
#include <cuda_runtime.h>
#include <cuda_fp16.h>
#include <math.h>

#define B_ 4
#define N_ 65536
#define K_ 16
#define D_ 8
#define EPS_ 1e-6f
#define SLOPE_ 0.2f

// 32B record per point: [x,y,z,pad (fp32) | f0..f7 (fp16)]
__device__ float4 g_rec[(size_t)B_ * N_ * 2];
__device__ double g_sums[16];                 // sum_y[0..7], sum_y2[8..15]

// 256-bit global load (sm_100+): whole 32B record in ONE instruction = ONE L1 wavefront
__device__ __forceinline__ void ldg256(const float4* p, float4& a, float4& b) {
    asm volatile(
        "ld.global.v8.b32 {%0,%1,%2,%3,%4,%5,%6,%7}, [%8];"
        : "=f"(a.x), "=f"(a.y), "=f"(a.z), "=f"(a.w),
          "=f"(b.x), "=f"(b.y), "=f"(b.z), "=f"(b.w)
        : "l"(p));
}

// per-block weight transform: [0..7]=W0, [8..31]=A(ext), [32..55]=C(nb), [56..63]=bias
__device__ __forceinline__ void load_wp_shared(float* s_wp,
                                               const float* __restrict__ conv_w,
                                               const float* __restrict__ conv_b) {
    if (threadIdx.x < 8) {
        int o = threadIdx.x;
        const float* w = conv_w + o * 10;
        s_wp[o] = w[0];
        s_wp[8 + o*3 + 0] = w[1] + w[4];
        s_wp[8 + o*3 + 1] = w[2] + w[5];
        s_wp[8 + o*3 + 2] = w[3] + w[6];
        s_wp[32 + o*3 + 0] = w[7] - w[1];
        s_wp[32 + o*3 + 1] = w[8] - w[2];
        s_wp[32 + o*3 + 2] = w[9] - w[3];
        s_wp[56 + o] = conv_b[o];
    }
}

// ---------------- Pass 0a: pack coords half of record; block0 zeros stats ----------------
__global__ void __launch_bounds__(256) k0a_coords(const float* __restrict__ coords) {
    if (blockIdx.x == 0 && threadIdx.x < 16) g_sums[threadIdx.x] = 0.0;
    int t = blockIdx.x * blockDim.x + threadIdx.x;
    if (t >= B_ * N_) return;
    float cx = coords[(size_t)t * 3 + 0];
    float cy = coords[(size_t)t * 3 + 1];
    float cz = coords[(size_t)t * 3 + 2];
    g_rec[(size_t)t * 2] = make_float4(cx, cy, cz, 0.f);
}

// ---------------- Pass 0b: pack fp16 features half (runs concurrent with k0a/k1) ----------------
__global__ void __launch_bounds__(256) k0b_feats(const float* __restrict__ feats) {
    int t = blockIdx.x * blockDim.x + threadIdx.x;
    if (t >= B_ * N_) return;
    int b = t >> 16;
    int n = t & (N_ - 1);
    const float* fb = feats + (size_t)b * D_ * N_ + n;
    __half2 h01 = __floats2half2_rn(fb[0 * N_], fb[1 * N_]);
    __half2 h23 = __floats2half2_rn(fb[2 * N_], fb[3 * N_]);
    __half2 h45 = __floats2half2_rn(fb[4 * N_], fb[5 * N_]);
    __half2 h67 = __floats2half2_rn(fb[6 * N_], fb[7 * N_]);
    float4 hv;
    hv.x = __uint_as_float(*(const unsigned*)&h01);
    hv.y = __uint_as_float(*(const unsigned*)&h23);
    hv.z = __uint_as_float(*(const unsigned*)&h45);
    hv.w = __uint_as_float(*(const unsigned*)&h67);
    g_rec[(size_t)t * 2 + 1] = hv;
}

// ---------------- Pass 1: BN statistics (coords-half gathers; shared weights) ----------------
__global__ void __launch_bounds__(256, 6) k1_stats(const int* __restrict__ idx,
                                                   const float* __restrict__ conv_w,
                                                   const float* __restrict__ conv_b) {
    __shared__ float s_wp[64];
    __shared__ float ps[16];
    load_wp_shared(s_wp, conv_w, conv_b);
    if (threadIdx.x >= 8 && threadIdx.x < 24) ps[threadIdx.x - 8] = 0.f;
    __syncthreads();

    int t = blockIdx.x * blockDim.x + threadIdx.x;   // one (b,n) per thread
    int base = (t >> 16) << 16;
    const float4* rec = g_rec;
    float4 ext = rec[(size_t)t * 2];

    float e[8];
    #pragma unroll
    for (int o = 0; o < 8; o++)
        e[o] = s_wp[56 + o] + s_wp[8 + o*3] * ext.x + s_wp[9 + o*3] * ext.y
                            + s_wp[10 + o*3] * ext.z;

    float sy[8], sy2[8];
    #pragma unroll
    for (int o = 0; o < 8; o++) { sy[o] = 0.f; sy2[o] = 0.f; }

    const int4* ip = (const int4*)idx + (size_t)t * 4;
    #pragma unroll
    for (int kk = 0; kk < 4; kk++) {
        int4 j4 = ip[kk];
        int js[4] = {j4.x, j4.y, j4.z, j4.w};
        #pragma unroll
        for (int u = 0; u < 4; u++) {
            float4 nb = rec[(size_t)(base + js[u]) * 2];
            float rx = ext.x - nb.x, ry = ext.y - nb.y, rz = ext.z - nb.z;
            float d = sqrtf(rx * rx + ry * ry + rz * rz);
            #pragma unroll
            for (int o = 0; o < 8; o++) {
                float y = e[o] + s_wp[o] * d + s_wp[32 + o*3] * nb.x
                        + s_wp[33 + o*3] * nb.y + s_wp[34 + o*3] * nb.z;
                sy[o]  += y;
                sy2[o] += y * y;
            }
        }
    }

    #pragma unroll
    for (int o = 0; o < 8; o++) {
        #pragma unroll
        for (int off = 16; off > 0; off >>= 1) {
            sy[o]  += __shfl_down_sync(0xffffffffu, sy[o],  off);
            sy2[o] += __shfl_down_sync(0xffffffffu, sy2[o], off);
        }
    }
    if ((threadIdx.x & 31) == 0) {
        #pragma unroll
        for (int o = 0; o < 8; o++) {
            atomicAdd(&ps[o],     sy[o]);
            atomicAdd(&ps[8 + o], sy2[o]);
        }
    }
    __syncthreads();
    if (threadIdx.x < 16) atomicAdd(&g_sums[threadIdx.x], (double)ps[threadIdx.x]);
}

// ---------------- Pass 2: one thread per neighbour-PAIR; 256-bit gathers; float2 stores ----------------
__global__ void __launch_bounds__(256, 5) k3_out(const int* __restrict__ idx,
                                                 const float* __restrict__ conv_w,
                                                 const float* __restrict__ conv_b,
                                                 const float* __restrict__ gamma,
                                                 const float* __restrict__ beta,
                                                 float* __restrict__ out) {
    __shared__ float s_wp[64];
    __shared__ float s_bn[16];    // scale[0..7], shift[8..15]
    load_wp_shared(s_wp, conv_w, conv_b);
    if (threadIdx.x >= 32 && threadIdx.x < 40) {
        int o = threadIdx.x - 32;
        double M    = (double)B_ * N_ * K_;
        double mean = g_sums[o] / M;
        double var  = g_sums[8 + o] / M - mean * mean;
        float  sc   = (float)((double)gamma[o] / sqrt(var + (double)EPS_));
        s_bn[o]     = sc;
        s_bn[8 + o] = beta[o] - (float)mean * sc;
    }
    __syncthreads();

    int t  = blockIdx.x * blockDim.x + threadIdx.x;  // [0, B*N*K/2)
    int pn = t >> 3;               // b*N + n
    int b  = pn >> 16;

    int2 j2 = ((const int2*)idx)[t];
    float4 nb0, hf0, nb1, hf1;
    ldg256(g_rec + ((size_t)((b << 16) | j2.x) << 1), nb0, hf0);
    ldg256(g_rec + ((size_t)((b << 16) | j2.y) << 1), nb1, hf1);

    float4 ext = g_rec[(size_t)pn << 1];            // broadcast within warp
    float rx0 = ext.x - nb0.x, ry0 = ext.y - nb0.y, rz0 = ext.z - nb0.z;
    float rx1 = ext.x - nb1.x, ry1 = ext.y - nb1.y, rz1 = ext.z - nb1.z;
    float d0 = sqrtf(rx0 * rx0 + ry0 * ry0 + rz0 * rz0);
    float d1 = sqrtf(rx1 * rx1 + ry1 * ry1 + rz1 * rz1);

    float e[8];
    #pragma unroll
    for (int o = 0; o < 8; o++)
        e[o] = s_wp[56 + o] + s_wp[8 + o*3] * ext.x + s_wp[9 + o*3] * ext.y
                            + s_wp[10 + o*3] * ext.z;

    // unpack fp16 features of both neighbours
    float2 fa[4], fb4[4];
    {
        const unsigned* u0 = (const unsigned*)&hf0;
        const unsigned* u1 = (const unsigned*)&hf1;
        #pragma unroll
        for (int q = 0; q < 4; q++) {
            fa[q]  = __half22float2(*(const __half2*)&u0[q]);
            fb4[q] = __half22float2(*(const __half2*)&u1[q]);
        }
    }

    const size_t plane = (size_t)N_ * K_;           // 1,048,576
    size_t inner = ((size_t)(t & (int)(plane / 2 - 1))) * 2;  // n*K + kpair*2
    float* o1 = out + (size_t)b * 16 * plane + inner;                          // (B,16,N,K)
    float* o2 = out + (size_t)B_ * 16 * plane + (size_t)b * 8 * plane + inner; // (B,8,N,K)

    // neighbour-feature channels 0..7: float2 {c(n0), c(n1)}
    #pragma unroll
    for (int q = 0; q < 4; q++) {
        __stcs((float2*)(o1 + (size_t)(2 * q + 0) * plane), make_float2(fa[q].x, fb4[q].x));
        __stcs((float2*)(o1 + (size_t)(2 * q + 1) * plane), make_float2(fa[q].y, fb4[q].y));
    }

    // BN + LeakyReLU channels
    #pragma unroll
    for (int o = 0; o < 8; o++) {
        float y0 = e[o] + s_wp[o] * d0 + s_wp[32 + o*3] * nb0.x
                 + s_wp[33 + o*3] * nb0.y + s_wp[34 + o*3] * nb0.z;
        float y1 = e[o] + s_wp[o] * d1 + s_wp[32 + o*3] * nb1.x
                 + s_wp[33 + o*3] * nb1.y + s_wp[34 + o*3] * nb1.z;
        float z0 = fmaf(y0, s_bn[o], s_bn[8 + o]);
        float z1 = fmaf(y1, s_bn[o], s_bn[8 + o]);
        z0 = fmaxf(z0, SLOPE_ * z0);
        z1 = fmaxf(z1, SLOPE_ * z1);
        float2 zz = make_float2(z0, z1);
        __stcs((float2*)(o1 + (size_t)(8 + o) * plane), zz);
        __stcs((float2*)(o2 + (size_t)o * plane), zz);
    }
}

extern "C" void kernel_launch(void* const* d_in, const int* in_sizes, int n_in,
                              void* d_out, int out_size) {
    const float* coords = (const float*)d_in[0];
    const float* feats  = (const float*)d_in[1];
    const int*   idx    = (const int*)d_in[2];
    const float* conv_w = (const float*)d_in[3];
    const float* conv_b = (const float*)d_in[4];
    const float* gamma  = (const float*)d_in[5];
    const float* beta   = (const float*)d_in[6];
    float* out = (float*)d_out;

    static cudaStream_t s1 = nullptr;
    static cudaEvent_t ev_fork = nullptr, ev_join = nullptr;
    if (s1 == nullptr) {
        cudaStreamCreateWithFlags(&s1, cudaStreamNonBlocking);
        cudaEventCreateWithFlags(&ev_fork, cudaEventDisableTiming);
        cudaEventCreateWithFlags(&ev_join, cudaEventDisableTiming);
    }

    cudaStream_t s0 = 0;

    // fork at entry: feature packing (DRAM-read bound) overlaps coords pack + stats
    cudaEventRecord(ev_fork, s0);
    cudaStreamWaitEvent(s1, ev_fork, 0);
    k0b_feats<<<(B_ * N_ + 255) / 256, 256, 0, s1>>>(feats);

    k0a_coords<<<(B_ * N_ + 255) / 256, 256, 0, s0>>>(coords);
    k1_stats<<<(B_ * N_) / 256, 256, 0, s0>>>(idx, conv_w, conv_b);

    // join: k3 needs both feature records and stats
    cudaEventRecord(ev_join, s1);
    cudaStreamWaitEvent(s0, ev_join, 0);
    k3_out<<<(B_ * N_ * K_ / 2) / 256, 256, 0, s0>>>(idx, conv_w, conv_b, gamma, beta, out);
}

// round 16
// speedup vs baseline: 1.2999x; 1.0216x over previous
#include <cuda_runtime.h>
#include <cuda_fp16.h>
#include <math.h>

#define B_ 4
#define N_ 65536
#define K_ 16
#define D_ 8
#define EPS_ 1e-6f
#define SLOPE_ 0.2f

// 32B record per point: [x,y,z,pad (fp32) | f0..f7 (fp16)]
__device__ float4 g_rec[(size_t)B_ * N_ * 2];
__device__ double g_sums[16];                 // sum_y[0..7], sum_y2[8..15]

// 256-bit global load (sm_100+): whole 32B record in ONE instruction = ONE L1 wavefront
__device__ __forceinline__ void ldg256(const float4* p, float4& a, float4& b) {
    asm volatile(
        "ld.global.v8.b32 {%0,%1,%2,%3,%4,%5,%6,%7}, [%8];"
        : "=f"(a.x), "=f"(a.y), "=f"(a.z), "=f"(a.w),
          "=f"(b.x), "=f"(b.y), "=f"(b.z), "=f"(b.w)
        : "l"(p));
}

// per-block weight transform: [0..7]=W0, [8..31]=A(ext), [32..55]=C(nb), [56..63]=bias
__device__ __forceinline__ void load_wp_shared(float* s_wp,
                                               const float* __restrict__ conv_w,
                                               const float* __restrict__ conv_b) {
    if (threadIdx.x < 8) {
        int o = threadIdx.x;
        const float* w = conv_w + o * 10;
        s_wp[o] = w[0];
        s_wp[8 + o*3 + 0] = w[1] + w[4];
        s_wp[8 + o*3 + 1] = w[2] + w[5];
        s_wp[8 + o*3 + 2] = w[3] + w[6];
        s_wp[32 + o*3 + 0] = w[7] - w[1];
        s_wp[32 + o*3 + 1] = w[8] - w[2];
        s_wp[32 + o*3 + 2] = w[9] - w[3];
        s_wp[56 + o] = conv_b[o];
    }
}

// ---------------- Pass 0a: pack coords half of record; block0 zeros stats ----------------
__global__ void __launch_bounds__(256) k0a_coords(const float* __restrict__ coords) {
    if (blockIdx.x == 0 && threadIdx.x < 16) g_sums[threadIdx.x] = 0.0;
    int t = blockIdx.x * blockDim.x + threadIdx.x;
    if (t >= B_ * N_) return;
    float cx = coords[(size_t)t * 3 + 0];
    float cy = coords[(size_t)t * 3 + 1];
    float cz = coords[(size_t)t * 3 + 2];
    g_rec[(size_t)t * 2] = make_float4(cx, cy, cz, 0.f);
}

// ---------------- Pass 0b: pack fp16 features half (runs concurrent with k0a/k1) ----------------
__global__ void __launch_bounds__(256) k0b_feats(const float* __restrict__ feats) {
    int t = blockIdx.x * blockDim.x + threadIdx.x;
    if (t >= B_ * N_) return;
    int b = t >> 16;
    int n = t & (N_ - 1);
    const float* fb = feats + (size_t)b * D_ * N_ + n;
    __half2 h01 = __floats2half2_rn(fb[0 * N_], fb[1 * N_]);
    __half2 h23 = __floats2half2_rn(fb[2 * N_], fb[3 * N_]);
    __half2 h45 = __floats2half2_rn(fb[4 * N_], fb[5 * N_]);
    __half2 h67 = __floats2half2_rn(fb[6 * N_], fb[7 * N_]);
    float4 hv;
    hv.x = __uint_as_float(*(const unsigned*)&h01);
    hv.y = __uint_as_float(*(const unsigned*)&h23);
    hv.z = __uint_as_float(*(const unsigned*)&h45);
    hv.w = __uint_as_float(*(const unsigned*)&h67);
    g_rec[(size_t)t * 2 + 1] = hv;
}

// ---------------- Pass 1: BN statistics; one thread per (point, k-half) = 8 neighbours ----------------
__global__ void __launch_bounds__(256, 6) k1_stats(const int* __restrict__ idx,
                                                   const float* __restrict__ conv_w,
                                                   const float* __restrict__ conv_b) {
    __shared__ float s_wp[64];
    __shared__ float ps[16];
    load_wp_shared(s_wp, conv_w, conv_b);
    if (threadIdx.x >= 8 && threadIdx.x < 24) ps[threadIdx.x - 8] = 0.f;
    __syncthreads();

    int t  = blockIdx.x * blockDim.x + threadIdx.x;  // [0, B*N*2)
    int pn = t >> 1;                                 // b*N + n
    int base = (pn >> 16) << 16;
    const float4* rec = g_rec;
    float4 ext = rec[(size_t)pn * 2];

    float e[8];
    #pragma unroll
    for (int o = 0; o < 8; o++)
        e[o] = s_wp[56 + o] + s_wp[8 + o*3] * ext.x + s_wp[9 + o*3] * ext.y
                            + s_wp[10 + o*3] * ext.z;

    float sy[8], sy2[8];
    #pragma unroll
    for (int o = 0; o < 8; o++) { sy[o] = 0.f; sy2[o] = 0.f; }

    // 8 neighbours = 2 int4 groups (this thread's half of the k-list)
    const int4* ip = (const int4*)idx + ((size_t)pn * 4) + ((t & 1) << 1);
    #pragma unroll
    for (int kk = 0; kk < 2; kk++) {
        int4 j4 = ip[kk];
        int js[4] = {j4.x, j4.y, j4.z, j4.w};
        #pragma unroll
        for (int u = 0; u < 4; u++) {
            float4 nb = rec[(size_t)(base + js[u]) * 2];
            float rx = ext.x - nb.x, ry = ext.y - nb.y, rz = ext.z - nb.z;
            float d = sqrtf(rx * rx + ry * ry + rz * rz);
            #pragma unroll
            for (int o = 0; o < 8; o++) {
                float y = e[o] + s_wp[o] * d + s_wp[32 + o*3] * nb.x
                        + s_wp[33 + o*3] * nb.y + s_wp[34 + o*3] * nb.z;
                sy[o]  += y;
                sy2[o] += y * y;
            }
        }
    }

    #pragma unroll
    for (int o = 0; o < 8; o++) {
        #pragma unroll
        for (int off = 16; off > 0; off >>= 1) {
            sy[o]  += __shfl_down_sync(0xffffffffu, sy[o],  off);
            sy2[o] += __shfl_down_sync(0xffffffffu, sy2[o], off);
        }
    }
    if ((threadIdx.x & 31) == 0) {
        #pragma unroll
        for (int o = 0; o < 8; o++) {
            atomicAdd(&ps[o],     sy[o]);
            atomicAdd(&ps[8 + o], sy2[o]);
        }
    }
    __syncthreads();
    if (threadIdx.x < 16) atomicAdd(&g_sums[threadIdx.x], (double)ps[threadIdx.x]);
}

// ---------------- Pass 2: one thread per neighbour-PAIR; 256-bit gathers; float2 stores ----------------
__global__ void __launch_bounds__(256, 5) k3_out(const int* __restrict__ idx,
                                                 const float* __restrict__ conv_w,
                                                 const float* __restrict__ conv_b,
                                                 const float* __restrict__ gamma,
                                                 const float* __restrict__ beta,
                                                 float* __restrict__ out) {
    __shared__ float s_wp[64];
    __shared__ float s_bn[16];    // scale[0..7], shift[8..15]
    load_wp_shared(s_wp, conv_w, conv_b);
    if (threadIdx.x >= 32 && threadIdx.x < 40) {
        int o = threadIdx.x - 32;
        double M    = (double)B_ * N_ * K_;
        double mean = g_sums[o] / M;
        double var  = g_sums[8 + o] / M - mean * mean;
        float  sc   = (float)((double)gamma[o] / sqrt(var + (double)EPS_));
        s_bn[o]     = sc;
        s_bn[8 + o] = beta[o] - (float)mean * sc;
    }
    __syncthreads();

    int t  = blockIdx.x * blockDim.x + threadIdx.x;  // [0, B*N*K/2)
    int pn = t >> 3;               // b*N + n
    int b  = pn >> 16;

    int2 j2 = ((const int2*)idx)[t];
    float4 nb0, hf0, nb1, hf1;
    ldg256(g_rec + ((size_t)((b << 16) | j2.x) << 1), nb0, hf0);
    ldg256(g_rec + ((size_t)((b << 16) | j2.y) << 1), nb1, hf1);

    float4 ext = g_rec[(size_t)pn << 1];            // broadcast within warp
    float rx0 = ext.x - nb0.x, ry0 = ext.y - nb0.y, rz0 = ext.z - nb0.z;
    float rx1 = ext.x - nb1.x, ry1 = ext.y - nb1.y, rz1 = ext.z - nb1.z;
    float d0 = sqrtf(rx0 * rx0 + ry0 * ry0 + rz0 * rz0);
    float d1 = sqrtf(rx1 * rx1 + ry1 * ry1 + rz1 * rz1);

    float e[8];
    #pragma unroll
    for (int o = 0; o < 8; o++)
        e[o] = s_wp[56 + o] + s_wp[8 + o*3] * ext.x + s_wp[9 + o*3] * ext.y
                            + s_wp[10 + o*3] * ext.z;

    // unpack fp16 features of both neighbours
    float2 fa[4], fb4[4];
    {
        const unsigned* u0 = (const unsigned*)&hf0;
        const unsigned* u1 = (const unsigned*)&hf1;
        #pragma unroll
        for (int q = 0; q < 4; q++) {
            fa[q]  = __half22float2(*(const __half2*)&u0[q]);
            fb4[q] = __half22float2(*(const __half2*)&u1[q]);
        }
    }

    const size_t plane = (size_t)N_ * K_;           // 1,048,576
    size_t inner = ((size_t)(t & (int)(plane / 2 - 1))) * 2;  // n*K + kpair*2
    float* o1 = out + (size_t)b * 16 * plane + inner;                          // (B,16,N,K)
    float* o2 = out + (size_t)B_ * 16 * plane + (size_t)b * 8 * plane + inner; // (B,8,N,K)

    // neighbour-feature channels 0..7: float2 {c(n0), c(n1)}
    #pragma unroll
    for (int q = 0; q < 4; q++) {
        __stcs((float2*)(o1 + (size_t)(2 * q + 0) * plane), make_float2(fa[q].x, fb4[q].x));
        __stcs((float2*)(o1 + (size_t)(2 * q + 1) * plane), make_float2(fa[q].y, fb4[q].y));
    }

    // BN + LeakyReLU channels
    #pragma unroll
    for (int o = 0; o < 8; o++) {
        float y0 = e[o] + s_wp[o] * d0 + s_wp[32 + o*3] * nb0.x
                 + s_wp[33 + o*3] * nb0.y + s_wp[34 + o*3] * nb0.z;
        float y1 = e[o] + s_wp[o] * d1 + s_wp[32 + o*3] * nb1.x
                 + s_wp[33 + o*3] * nb1.y + s_wp[34 + o*3] * nb1.z;
        float z0 = fmaf(y0, s_bn[o], s_bn[8 + o]);
        float z1 = fmaf(y1, s_bn[o], s_bn[8 + o]);
        z0 = fmaxf(z0, SLOPE_ * z0);
        z1 = fmaxf(z1, SLOPE_ * z1);
        float2 zz = make_float2(z0, z1);
        __stcs((float2*)(o1 + (size_t)(8 + o) * plane), zz);
        __stcs((float2*)(o2 + (size_t)o * plane), zz);
    }
}

extern "C" void kernel_launch(void* const* d_in, const int* in_sizes, int n_in,
                              void* d_out, int out_size) {
    const float* coords = (const float*)d_in[0];
    const float* feats  = (const float*)d_in[1];
    const int*   idx    = (const int*)d_in[2];
    const float* conv_w = (const float*)d_in[3];
    const float* conv_b = (const float*)d_in[4];
    const float* gamma  = (const float*)d_in[5];
    const float* beta   = (const float*)d_in[6];
    float* out = (float*)d_out;

    static cudaStream_t s1 = nullptr;
    static cudaEvent_t ev_fork = nullptr, ev_join = nullptr;
    if (s1 == nullptr) {
        cudaStreamCreateWithFlags(&s1, cudaStreamNonBlocking);
        cudaEventCreateWithFlags(&ev_fork, cudaEventDisableTiming);
        cudaEventCreateWithFlags(&ev_join, cudaEventDisableTiming);
    }

    cudaStream_t s0 = 0;

    // fork at entry: feature packing (DRAM-read bound) overlaps coords pack + stats
    cudaEventRecord(ev_fork, s0);
    cudaStreamWaitEvent(s1, ev_fork, 0);
    k0b_feats<<<(B_ * N_ + 255) / 256, 256, 0, s1>>>(feats);

    k0a_coords<<<(B_ * N_ + 255) / 256, 256, 0, s0>>>(coords);
    k1_stats<<<(B_ * N_ * 2) / 256, 256, 0, s0>>>(idx, conv_w, conv_b);

    // join: k3 needs both feature records and stats
    cudaEventRecord(ev_join, s1);
    cudaStreamWaitEvent(s0, ev_join, 0);
    k3_out<<<(B_ * N_ * K_ / 2) / 256, 256, 0, s0>>>(idx, conv_w, conv_b, gamma, beta, out);
}